// round 14
// baseline (speedup 1.0000x reference)
#include <cuda_runtime.h>
#include <math.h>

// Problem constants (shapes fixed by the dataset)
#define BATCH 8
#define R 300
#define C 21
#define NC 20           // foreground classes
#define KPAD 21         // output pad size == num_classes
#define RW 10           // ceil(300/32) keep-bitmask words
#define NMS_T 0.3f
#define NCLS (BATCH * NC)   // 160 class-tasks

// Cross-kernel intermediates (allocation-free rule: device globals)
__device__ float4   g_sbx[NCLS * R];          // sorted+clipped boxes per class-task
__device__ float    g_area[NCLS * R];         // areas in sorted order
__device__ int      g_V[NCLS];                // valid counts
__device__ unsigned g_mask[NCLS * R * RW];    // suppression masks (1.92 MB, L2)
__device__ unsigned g_keep[NCLS * RW];        // keep bitmasks
__device__ int      g_ctr[BATCH];             // arrival counters (self-resetting)

// ---------------------------------------------------------------------------
// Kernel 1: decode + clip + compact + rank sort.  grid = 160, block = 512.
// ---------------------------------------------------------------------------
__global__ __launch_bounds__(512) void k_decode_sort(
    const float* __restrict__ cls_prob,   // [B,R,C]
    const float* __restrict__ rois,       // [B,R,5]
    const float* __restrict__ bbox_pred,  // [B,R,4C]
    const float* __restrict__ im_info,    // [B,3]
    const float* __restrict__ thr_arr)    // [C]
{
    __shared__ float4 box_sh[R];               // decoded boxes by original index
    __shared__ unsigned long long ckeys[R];    // compacted valid keys (set only)
    __shared__ int sV;

    const int cls = blockIdx.x;
    const int b   = cls / NC;
    const int cc  = cls % NC;
    const int c   = cc + 1;
    const int tl  = threadIdx.x;
    const int lane = tl & 31;

    if (tl == 0) sV = 0;

    const float thr = thr_arr[c];
    const float H1 = im_info[b * 3 + 0] - 1.0f;
    const float W1 = im_info[b * 3 + 1] - 1.0f;

    // ---- decode + clip + key (arithmetic identical to the R1 passing kernel) ----
    int valid = 0;
    unsigned long long key = ~0ULL;
    const int r = tl;
    if (r < R) {
        const float* rp = rois + (size_t)(b * R + r) * 5;
        float x1 = rp[1], y1 = rp[2], x2 = rp[3], y2 = rp[4];
        float w  = x2 - x1 + 1.0f;
        float h  = y2 - y1 + 1.0f;
        float cx = x1 + 0.5f * w;
        float cy = y1 + 0.5f * h;

        const float4 d4 = *reinterpret_cast<const float4*>(
            bbox_pred + (size_t)(b * R + r) * (4 * C) + 4 * c);
        float d0 = d4.x * 0.1f;
        float d1 = d4.y * 0.1f;
        float d2 = d4.z * 0.2f;
        float d3 = d4.w * 0.2f;

        float pcx = d0 * w + cx;
        float pcy = d1 * h + cy;
        float pw  = expf(d2) * w;
        float ph  = expf(d3) * h;

        float bx1 = fminf(fmaxf(pcx - 0.5f * pw, 0.0f), W1);
        float by1 = fminf(fmaxf(pcy - 0.5f * ph, 0.0f), H1);
        float bx2 = fminf(fmaxf(pcx + 0.5f * pw, 0.0f), W1);
        float by2 = fminf(fmaxf(pcy + 0.5f * ph, 0.0f), H1);
        box_sh[r] = make_float4(bx1, by1, bx2, by2);

        float s = cls_prob[(size_t)(b * R + r) * C + c];
        valid = (s > thr) ? 1 : 0;

        // monotone float->uint, inverted => ascending sort == descending score,
        // low 32 bits = original index (stable tie-break).
        unsigned u = __float_as_uint(s);
        unsigned m = (u & 0x80000000u) ? ~u : (u | 0x80000000u);
        key = (((unsigned long long)(~m)) << 32) | (unsigned)r;
    }
    __syncthreads();   // sV init visible

    // ---- UNSTABLE compaction (order-free: rank sort is a key-set operation,
    //      keys unique => ranks are a permutation) ----
    unsigned bal = __ballot_sync(0xffffffffu, valid);
    {
        int cntw = __popc(bal);
        int base = 0;
        if (lane == 0 && cntw) base = atomicAdd(&sV, cntw);
        base = __shfl_sync(0xffffffffu, base, 0);
        if (valid) {
            int pos = base + __popc(bal & ((1u << lane) - 1u));
            ckeys[pos] = key;
        }
    }
    __syncthreads();
    const int V = sV;

    // ---- enumeration (rank) sort; scatter straight to device globals ----
    if (V > 0) {
        if (V <= 256) {
            // 2 threads per key
            int p = tl >> 1;
            int pc = (p < V) ? p : (V - 1);
            unsigned long long kp = ckeys[pc];
            int hh = tl & 1;
            int Vh = (V + 1) >> 1;
            int jlo = hh ? Vh : 0;
            int jhi = hh ? V : Vh;
            int rk = 0;
            #pragma unroll 4
            for (int j = jlo; j < jhi; j++)
                rk += (ckeys[j] < kp);
            rk += __shfl_xor_sync(0xffffffffu, rk, 1);
            if (hh == 0 && p < V) {
                int orig = (int)(kp & 0xFFFFFFFFu);
                float4 bb = box_sh[orig];
                g_sbx[cls * R + rk]  = bb;
                g_area[cls * R + rk] = (bb.z - bb.x + 1.0f) * (bb.w - bb.y + 1.0f);
            }
        } else {
            if (tl < V) {
                unsigned long long kp = ckeys[tl];
                int rk = 0;
                #pragma unroll 4
                for (int j = 0; j < V; j++)
                    rk += (ckeys[j] < kp);
                int orig = (int)(kp & 0xFFFFFFFFu);
                float4 bb = box_sh[orig];
                g_sbx[cls * R + rk]  = bb;
                g_area[cls * R + rk] = (bb.z - bb.x + 1.0f) * (bb.w - bb.y + 1.0f);
            }
        }
    }
    if (tl == 0) g_V[cls] = V;
}

// ---------------------------------------------------------------------------
// Kernel 2: suppression masks (the V^2 phase).  grid = 160, block = 512.
// Reads sorted boxes via __ldg (L1-cached broadcast); writes masks to L2.
// ---------------------------------------------------------------------------
__global__ __launch_bounds__(512) void k_iou()
{
    const int cls = blockIdx.x;
    const int tl  = threadIdx.x;
    const int lane = tl & 31;
    const int wl  = tl >> 5;          // 0..15

    const int V  = g_V[cls];
    const int VW = (V + 31) >> 5;
    const unsigned tailm = (V & 31) ? ((1u << (V & 31)) - 1u) : ~0u;
    const float4* __restrict__ sb = g_sbx + (size_t)cls * R;
    const float*  __restrict__ ar = g_area + (size_t)cls * R;
    unsigned* __restrict__ mk = g_mask + (size_t)cls * R * RW;

    const int PT = (V + 1) >> 1;      // pair tasks
    for (int task = wl; task < PT; task += 16) {
        const int i  = task << 1;
        const int i2 = i + 1;
        const bool has2 = (i2 < V);
        const int iw0 = i >> 5;                           // == i2 >> 5 (i even)
        const unsigned am1 = ~((2u << (i  & 31)) - 1u);   // bits j>i
        const unsigned am2 = ~((2u << (i2 & 31)) - 1u);   // bits j>i2
        float4 bi  = __ldg(&sb[i]);
        float  ai  = __ldg(&ar[i]);
        float4 bi2 = __ldg(&sb[has2 ? i2 : i]);
        float  ai2 = __ldg(&ar[has2 ? i2 : i]);
        for (int jw = iw0; jw < VW; jw++) {
            int j  = (jw << 5) + lane;
            int jc = min(j, V - 1);
            float4 bj = __ldg(&sb[jc]);
            float  aj = __ldg(&ar[jc]);

            bool sup1, sup2;
            {
                float ix1 = fmaxf(bi.x, bj.x);
                float iy1 = fmaxf(bi.y, bj.y);
                float ix2 = fminf(bi.z, bj.z);
                float iy2 = fminf(bi.w, bj.w);
                float iw = fmaxf(ix2 - ix1 + 1.0f, 0.0f);
                float ih = fmaxf(iy2 - iy1 + 1.0f, 0.0f);
                float inter = iw * ih;
                float asum = ai + aj;
                float diff = fmaf(inter, 1.0f + NMS_T, -NMS_T * asum);
                sup1 = diff > 0.0f;
                float un = asum - inter;
                if (fabsf(diff) <= 1e-5f * un)
                    sup1 = (inter / un) > NMS_T;   // rare exact fallback
            }
            {
                float ix1 = fmaxf(bi2.x, bj.x);
                float iy1 = fmaxf(bi2.y, bj.y);
                float ix2 = fminf(bi2.z, bj.z);
                float iy2 = fminf(bi2.w, bj.w);
                float iw = fmaxf(ix2 - ix1 + 1.0f, 0.0f);
                float ih = fmaxf(iy2 - iy1 + 1.0f, 0.0f);
                float inter = iw * ih;
                float asum = ai2 + aj;
                float diff = fmaf(inter, 1.0f + NMS_T, -NMS_T * asum);
                sup2 = diff > 0.0f;
                float un = asum - inter;
                if (fabsf(diff) <= 1e-5f * un)
                    sup2 = (inter / un) > NMS_T;   // rare exact fallback
            }
            unsigned bits1 = __ballot_sync(0xffffffffu, sup1);
            unsigned bits2 = __ballot_sync(0xffffffffu, sup2);
            if (lane == 0) {
                unsigned vm = (jw == VW - 1) ? tailm : ~0u;
                unsigned m1 = (jw == iw0) ? (vm & am1) : vm;
                mk[i * RW + jw] = bits1 & m1;
                if (has2) {
                    unsigned m2 = (jw == iw0) ? (vm & am2) : vm;
                    mk[i2 * RW + jw] = bits2 & m2;
                }
            }
        }
    }
}

// ---------------------------------------------------------------------------
// Kernel 3: peel NMS + per-image selection.  grid = 160, block = 512.
// ---------------------------------------------------------------------------
__global__ __launch_bounds__(512) void k_peel_select(
    float* __restrict__ out, int out_size)
{
    __shared__ unsigned mask_sh[R][RW];
    __shared__ unsigned slive[RW], skept[RW], sknew[RW];
    __shared__ int sOld;
    __shared__ unsigned skw[NC][RW];
    __shared__ int sexcl[32];

    const int cls = blockIdx.x;
    const int b   = cls / NC;
    const int tl  = threadIdx.x;
    const int lane = tl & 31;
    const int wl  = tl >> 5;

    const int V = g_V[cls];
    const unsigned* __restrict__ mk = g_mask + (size_t)cls * R * RW;

    // stage masks into smem, zero-filling below-diagonal words (not written by k2)
    for (int idx = tl; idx < V * RW; idx += 512) {
        int i = idx / RW;            // RW is a literal: mul-shift, cheap
        int w = idx - i * RW;
        mask_sh[i][w] = (w < (i >> 5)) ? 0u : __ldcg(&mk[idx]);
    }
    if (tl < RW) {
        int lo = tl << 5, hi = min(V, lo + 32);
        unsigned lv = 0;
        if (hi > lo) lv = (hi - lo == 32) ? 0xffffffffu : ((1u << (hi - lo)) - 1u);
        slive[tl] = lv;
        skept[tl] = 0u;
    }
    __syncthreads();

    // ---- exact parallel peeling NMS (identical to the R12 passing kernel) ----
    int alive = (V > 0);
    while (alive) {
        unsigned acc = 0;
        if (wl < RW) {
            for (int i = lane; i < V; i += 32)
                if ((slive[i >> 5] >> (i & 31)) & 1u) acc |= mask_sh[i][wl];
            #pragma unroll
            for (int off = 16; off > 0; off >>= 1)
                acc |= __shfl_down_sync(0xffffffffu, acc, off);
            if (lane == 0) {
                unsigned kn = slive[wl] & ~acc;
                sknew[wl] = kn;
                skept[wl] |= kn;
            }
        }
        __syncthreads();
        unsigned acc2 = 0;
        if (wl < RW) {
            for (int i = lane; i < V; i += 32)
                if ((sknew[i >> 5] >> (i & 31)) & 1u) acc2 |= mask_sh[i][wl];
            #pragma unroll
            for (int off = 16; off > 0; off >>= 1)
                acc2 |= __shfl_down_sync(0xffffffffu, acc2, off);
            if (lane == 0)
                slive[wl] = slive[wl] & acc & ~acc2;
        }
        __syncthreads();
        unsigned any = 0;
        #pragma unroll
        for (int w2 = 0; w2 < RW; w2++) any |= slive[w2];
        alive = (any != 0u);
    }
    if (tl < RW)
        __stcg(&g_keep[cls * RW + tl], skept[tl]);

    // ---- release writes, arrive; 20th-arriving class block does selection ----
    __threadfence();
    __syncthreads();
    if (tl == 0) {
        sOld = atomicAdd(&g_ctr[b], 1);
        __threadfence();
    }
    __syncthreads();

    if (sOld == NC - 1 && tl < 32) {
        int clsx = lane;     // 0..19 valid
        int cnt = 0;
        if (clsx < NC) {
            #pragma unroll
            for (int w = 0; w < RW; w++) {
                unsigned kwv = __ldcg(&g_keep[(b * NC + clsx) * RW + w]);
                skw[clsx][w] = kwv;
                cnt += __popc(kwv);
            }
        }
        // warp inclusive scan of counts
        int incl = cnt;
        #pragma unroll
        for (int off = 1; off < 32; off <<= 1) {
            int n = __shfl_up_sync(0xffffffffu, incl, off);
            if (lane >= off) incl += n;
        }
        int total = __shfl_sync(0xffffffffu, incl, 31);
        sexcl[lane] = incl - cnt;
        __syncwarp();

        // zero this image's [K,5] slab
        for (int i = lane; i < KPAD * 5; i += 32)
            out[b * (KPAD * 5) + i] = 0.0f;
        __syncwarp();

        // slot-parallel emit: lane s owns output slot s
        int s = lane;
        int lim = min(total, KPAD);
        if (s < lim) {
            int cl = 0;
            #pragma unroll
            for (int c2 = 1; c2 < NC; c2++)
                if (sexcl[c2] <= s) cl = c2;
            int q = s - sexcl[cl];
            int w = 0;
            #pragma unroll
            for (int ww = 0; ww < RW; ww++) {
                int pc = __popc(skw[cl][ww]);
                bool here = (q < pc);
                if (!here) q -= pc;
                if (here) { w = ww; break; }
            }
            unsigned word = skw[cl][w];
            #pragma unroll
            for (int k = 0; k < 31; k++)
                if (k < q) word &= word - 1u;
            int bit = __ffs(word) - 1;
            float4 bb = __ldcg(&g_sbx[(size_t)(b * NC + cl) * R + (w << 5) + bit]);
            float* o = out + b * (KPAD * 5) + s * 5;
            o[0] = bb.x; o[1] = bb.y; o[2] = bb.z; o[3] = bb.w;
            o[4] = (float)(cl + 1);
        }
        if (lane == 0) {
            int nbase = BATCH * KPAD * 5;
            if (out_size >= nbase + BATCH)
                out[nbase + b] = (float)lim;
            g_ctr[b] = 0;   // self-reset for next graph replay
        }
    }
}

// ---------------------------------------------------------------------------
extern "C" void kernel_launch(void* const* d_in, const int* in_sizes, int n_in,
                              void* d_out, int out_size)
{
    (void)in_sizes; (void)n_in;
    const float* cls_prob  = (const float*)d_in[0];
    const float* rois      = (const float*)d_in[1];
    const float* bbox_pred = (const float*)d_in[2];
    const float* im_info   = (const float*)d_in[3];
    const float* thr       = (const float*)d_in[4];

    k_decode_sort<<<NCLS, 512>>>(cls_prob, rois, bbox_pred, im_info, thr);
    k_iou<<<NCLS, 512>>>();
    k_peel_select<<<NCLS, 512>>>((float*)d_out, out_size);
}

// round 15
// speedup vs baseline: 1.4174x; 1.4174x over previous
#include <cuda_runtime.h>
#include <math.h>

// Problem constants (shapes fixed by the dataset)
#define BATCH 8
#define R 300
#define C 21
#define NC 20           // foreground classes
#define KPAD 21         // output pad size == num_classes
#define RW 10           // ceil(300/32) keep-bitmask words
#define NMS_T 0.3f
#define NT 1024         // threads per block (2 independent halves of 512)
#define HT 512          // threads per half
#define NW 16           // warps per half
#define NPAIR (NC / 2)  // class pairs per image = blocks per image

// Cross-block intermediates (allocation-free rule: device globals)
__device__ float4   g_sb[BATCH * NC * R];      // sorted+clipped boxes per (b,class)
__device__ unsigned g_keep[BATCH * NC * RW];   // keep bitmask per (b,class)
__device__ int      g_ctr[BATCH];              // arrival counters (self-resetting)

struct Smem {
    float4  box[2][R];             // decoded boxes by original index
    float4  sb[2][R];              // boxes in sorted order (valid prefix)
    unsigned long long ckeys[2][R];// compacted valid keys, index order
    float   area[2][R];            // areas in sorted order
    unsigned mask[2][R][RW];       // suppression bitmask (valid prefix)
    int warpcnt[2][NW];
    int warpoff[2][NW];
    int sV[2];
    int sOld[2];
    unsigned slive[2][RW], skept[2][RW], sknew[2][RW];
    unsigned skw[NC][RW];          // tail selection scratch
    int sexcl[32];
};

// Per-half barrier: ids 1 and 2 (0 is reserved for __syncthreads).
__device__ __forceinline__ void bar_half(int half) {
    asm volatile("bar.sync %0, %1;" :: "r"(half + 1), "r"(HT) : "memory");
}

__global__ __launch_bounds__(NT, 1) void fused_nms_kernel(
    const float* __restrict__ cls_prob,   // [B,R,C]
    const float* __restrict__ rois,       // [B,R,5]
    const float* __restrict__ bbox_pred,  // [B,R,4C]
    const float* __restrict__ im_info,    // [B,3]
    const float* __restrict__ thr_arr,    // [C]
    float* __restrict__ out, int out_size)
{
    extern __shared__ __align__(16) unsigned char smem_raw[];
    Smem& S = *reinterpret_cast<Smem*>(smem_raw);

    const int blk  = blockIdx.x;
    const int b    = blk / NPAIR;
    const int t    = threadIdx.x;
    const int half = t >> 9;                 // 0 or 1: which class of the pair
    const int tl   = t & (HT - 1);           // thread id within half
    const int lane = t & 31;
    const int wl   = tl >> 5;                // warp id within half (0..15)
    const int cc   = (blk % NPAIR) * 2 + half;   // 0..19
    const int c    = cc + 1;                 // class id 1..20

    const float thr = thr_arr[c];
    const float H1 = im_info[b * 3 + 0] - 1.0f;
    const float W1 = im_info[b * 3 + 1] - 1.0f;

    // ---- decode + clip + key (one row per thread; arithmetic identical to R1) ----
    int valid = 0;
    unsigned long long key = ~0ULL;
    const int r = tl;
    if (r < R) {
        const float* rp = rois + (size_t)(b * R + r) * 5;
        float x1 = rp[1], y1 = rp[2], x2 = rp[3], y2 = rp[4];
        float w  = x2 - x1 + 1.0f;
        float h  = y2 - y1 + 1.0f;
        float cx = x1 + 0.5f * w;
        float cy = y1 + 0.5f * h;

        // 16B-aligned: byte offset = 336*(b*R+r) + 16*c
        const float4 d4 = *reinterpret_cast<const float4*>(
            bbox_pred + (size_t)(b * R + r) * (4 * C) + 4 * c);
        float d0 = d4.x * 0.1f;
        float d1 = d4.y * 0.1f;
        float d2 = d4.z * 0.2f;
        float d3 = d4.w * 0.2f;

        float pcx = d0 * w + cx;
        float pcy = d1 * h + cy;
        float pw  = expf(d2) * w;
        float ph  = expf(d3) * h;

        float bx1 = fminf(fmaxf(pcx - 0.5f * pw, 0.0f), W1);
        float by1 = fminf(fmaxf(pcy - 0.5f * ph, 0.0f), H1);
        float bx2 = fminf(fmaxf(pcx + 0.5f * pw, 0.0f), W1);
        float by2 = fminf(fmaxf(pcy + 0.5f * ph, 0.0f), H1);
        S.box[half][r] = make_float4(bx1, by1, bx2, by2);

        float s = cls_prob[(size_t)(b * R + r) * C + c];
        valid = (s > thr) ? 1 : 0;

        // monotone float->uint, inverted => ascending sort == descending score,
        // low 32 bits = original index (stable tie-break).
        unsigned u = __float_as_uint(s);
        unsigned m = (u & 0x80000000u) ? ~u : (u | 0x80000000u);
        key = (((unsigned long long)(~m)) << 32) | (unsigned)r;
    }

    // ---- stable compaction of valid rows per half (index order preserved) ----
    unsigned bal = __ballot_sync(0xffffffffu, valid);
    if (lane == 0) S.warpcnt[half][wl] = __popc(bal);
    bar_half(half);
    if (tl < NW) {
        int v = S.warpcnt[half][tl];
        int incl = v;
        #pragma unroll
        for (int off = 1; off < NW; off <<= 1) {
            int n = __shfl_up_sync(0x0000ffffu, incl, off);
            if (tl >= off) incl += n;
        }
        S.warpoff[half][tl] = incl - v;
        if (tl == NW - 1) S.sV[half] = incl;
    }
    bar_half(half);
    const int V  = S.sV[half];
    const int VW = (V + 31) >> 5;

    if (valid) {
        int pos = S.warpoff[half][wl] + __popc(bal & ((1u << lane) - 1u));
        S.ckeys[half][pos] = key;
    }
    bar_half(half);

    // ---- enumeration (rank) sort over the V compacted keys (per half) ----
    if (V > 0) {
        if (V <= 256) {
            // 2 threads per key: even counts [0,Vh), odd counts [Vh,V)
            int p = tl >> 1;
            int pc = (p < V) ? p : (V - 1);
            unsigned long long kp = S.ckeys[half][pc];
            int hh = tl & 1;
            int Vh = (V + 1) >> 1;
            int jlo = hh ? Vh : 0;
            int jhi = hh ? V : Vh;
            int rk = 0;
            #pragma unroll 4
            for (int j = jlo; j < jhi; j++)
                rk += (S.ckeys[half][j] < kp);
            rk += __shfl_xor_sync(0xffffffffu, rk, 1);
            if (hh == 0 && p < V) {
                int orig = (int)(kp & 0xFFFFFFFFu);
                float4 bb = S.box[half][orig];
                S.sb[half][rk] = bb;
                S.area[half][rk] = (bb.z - bb.x + 1.0f) * (bb.w - bb.y + 1.0f);
            }
        } else {
            if (tl < V) {
                unsigned long long kp = S.ckeys[half][tl];
                int rk = 0;
                #pragma unroll 4
                for (int j = 0; j < V; j++)
                    rk += (S.ckeys[half][j] < kp);
                int orig = (int)(kp & 0xFFFFFFFFu);
                float4 bb = S.box[half][orig];
                S.sb[half][rk] = bb;
                S.area[half][rk] = (bb.z - bb.x + 1.0f) * (bb.w - bb.y + 1.0f);
            }
        }
    }
    // pre-zero mask rows (peeling reads full rows, including below-diagonal words)
    for (int idx = tl; idx < V * RW; idx += HT)
        ((unsigned*)S.mask[half])[idx] = 0u;
    bar_half(half);

    // ---- publish sorted boxes (valid prefix) for cross-block selection ----
    if (tl < V)
        __stcg(&g_sb[(size_t)(b * NC + cc) * R + tl], S.sb[half][tl]);

    // ---- suppression bitmask, paired rows per warp, division-free compare ----
    //   iou > T  <=>  (1+T)*inter - T*(ai+aj) > 0 (reals). When |diff| is larger
    //   than 1e-5 * union (>> combined rounding), the fast form is exact;
    //   otherwise evaluate the reference's literal (inter/union) > T.
    //   The fallback is hoisted behind a warp-uniform ballot branch so the
    //   division path is BRANCHED OVER (not predicated in) when no lane needs it.
    for (int i = wl; i < V; i += 2 * NW) {
        const int i2 = i + NW;
        const bool has2 = (i2 < V);
        float4 bi  = S.sb[half][i];
        float  ai  = S.area[half][i];
        float4 bi2 = S.sb[half][has2 ? i2 : i];
        float  ai2 = S.area[half][has2 ? i2 : i];
        for (int jw = (i >> 5); jw < VW; jw++) {
            int j  = (jw << 5) + lane;
            int jc = (j < V) ? j : (V - 1);
            float4 bj = S.sb[half][jc];
            float  aj = S.area[half][jc];

            float inter1, un1, diff1, inter2, un2, diff2;
            bool sup1, sup2;
            {
                float ix1 = fmaxf(bi.x, bj.x);
                float iy1 = fmaxf(bi.y, bj.y);
                float ix2 = fminf(bi.z, bj.z);
                float iy2 = fminf(bi.w, bj.w);
                float iw = fmaxf(ix2 - ix1 + 1.0f, 0.0f);
                float ih = fmaxf(iy2 - iy1 + 1.0f, 0.0f);
                inter1 = iw * ih;
                float asum = ai + aj;
                diff1 = fmaf(inter1, 1.0f + NMS_T, -NMS_T * asum);
                un1   = asum - inter1;
                sup1  = diff1 > 0.0f;
            }
            {
                float ix1 = fmaxf(bi2.x, bj.x);
                float iy1 = fmaxf(bi2.y, bj.y);
                float ix2 = fminf(bi2.z, bj.z);
                float iy2 = fminf(bi2.w, bj.w);
                float iw = fmaxf(ix2 - ix1 + 1.0f, 0.0f);
                float ih = fmaxf(iy2 - iy1 + 1.0f, 0.0f);
                inter2 = iw * ih;
                float asum = ai2 + aj;
                diff2 = fmaf(inter2, 1.0f + NMS_T, -NMS_T * asum);
                un2   = asum - inter2;
                sup2  = diff2 > 0.0f;
            }
            // warp-uniform rare fallback: division executes only if some lane
            // is within the rounding guard band (prob ~1e-5 per pair)
            bool need1 = fabsf(diff1) <= 1e-5f * un1;
            bool need2 = fabsf(diff2) <= 1e-5f * un2;
            if (__ballot_sync(0xffffffffu, need1 || need2)) {
                if (need1) sup1 = (inter1 / un1) > NMS_T;
                if (need2) sup2 = (inter2 / un2) > NMS_T;
            }
            sup1 = sup1 && (j > i)  && (j < V);
            sup2 = sup2 && has2 && (j > i2) && (j < V);

            unsigned bits1 = __ballot_sync(0xffffffffu, sup1);
            unsigned bits2 = __ballot_sync(0xffffffffu, sup2);
            if (lane == 0) {
                S.mask[half][i][jw] = bits1;
                if (has2) S.mask[half][i2][jw] = bits2;  // zero below diag: harmless
            }
        }
    }

    // ---- init peeling state ----
    if (tl < RW) {
        int lo = tl << 5, hi = min(V, lo + 32);
        unsigned lv = 0;
        if (hi > lo) lv = (hi - lo == 32) ? 0xffffffffu : ((1u << (hi - lo)) - 1u);
        S.slive[half][tl] = lv;
        S.skept[half][tl] = 0u;
    }
    bar_half(half);   // orders slive/skept/mask writes for this half

    // ---- exact parallel peeling NMS: independent per half, 2 barriers/round ----
    int alive = (V > 0);
    while (alive) {
        unsigned acc = 0;
        if (wl < RW) {
            for (int i = lane; i < V; i += 32)
                if ((S.slive[half][i >> 5] >> (i & 31)) & 1u) acc |= S.mask[half][i][wl];
            #pragma unroll
            for (int off = 16; off > 0; off >>= 1)
                acc |= __shfl_down_sync(0xffffffffu, acc, off);
            if (lane == 0) {
                unsigned kn = S.slive[half][wl] & ~acc;
                S.sknew[half][wl] = kn;
                S.skept[half][wl] |= kn;
            }
        }
        bar_half(half);                    // sknew visible; slive still old
        unsigned acc2 = 0;
        if (wl < RW) {
            for (int i = lane; i < V; i += 32)
                if ((S.sknew[half][i >> 5] >> (i & 31)) & 1u) acc2 |= S.mask[half][i][wl];
            #pragma unroll
            for (int off = 16; off > 0; off >>= 1)
                acc2 |= __shfl_down_sync(0xffffffffu, acc2, off);
            if (lane == 0)
                S.slive[half][wl] = S.slive[half][wl] & acc & ~acc2;  // acc in reg
        }
        bar_half(half);                    // updated slive visible
        unsigned any = 0;
        #pragma unroll
        for (int w2 = 0; w2 < RW; w2++) any |= S.slive[half][w2];
        alive = (any != 0u);               // uniform within the half
    }
    if (tl < RW)
        __stcg(&g_keep[(b * NC + cc) * RW + tl], S.skept[half][tl]);

    // ---- release writes, arrive; 20th-arriving half does selection ----
    __threadfence();
    bar_half(half);
    if (tl == 0) {
        S.sOld[half] = atomicAdd(&g_ctr[b], 1);
        __threadfence();
    }
    bar_half(half);

    if (S.sOld[half] == NC - 1 && tl < 32) {
        int cls = lane;     // 0..19 valid
        int cnt = 0;
        if (cls < NC) {
            #pragma unroll
            for (int w = 0; w < RW; w++) {
                unsigned kwv = __ldcg(&g_keep[(b * NC + cls) * RW + w]);
                S.skw[cls][w] = kwv;
                cnt += __popc(kwv);
            }
        }
        // warp inclusive scan of counts
        int incl = cnt;
        #pragma unroll
        for (int off = 1; off < 32; off <<= 1) {
            int n = __shfl_up_sync(0xffffffffu, incl, off);
            if (lane >= off) incl += n;
        }
        int total = __shfl_sync(0xffffffffu, incl, 31);
        S.sexcl[lane] = incl - cnt;
        __syncwarp();

        // zero this image's [K,5] slab
        for (int i = lane; i < KPAD * 5; i += 32)
            out[b * (KPAD * 5) + i] = 0.0f;
        __syncwarp();

        // slot-parallel emit: lane s owns output slot s
        int s = lane;
        int lim = min(total, KPAD);
        if (s < lim) {
            int cl = 0;
            #pragma unroll
            for (int c2 = 1; c2 < NC; c2++)
                if (S.sexcl[c2] <= s) cl = c2;
            int q = s - S.sexcl[cl];
            int w = 0;
            #pragma unroll
            for (int ww = 0; ww < RW; ww++) {
                int pc = __popc(S.skw[cl][ww]);
                bool here = (q < pc);
                if (!here) q -= pc;
                if (here) { w = ww; break; }
            }
            unsigned word = S.skw[cl][w];
            #pragma unroll
            for (int k = 0; k < 31; k++)
                if (k < q) word &= word - 1u;
            int bit = __ffs(word) - 1;
            float4 bb = __ldcg(&g_sb[(size_t)(b * NC + cl) * R + (w << 5) + bit]);
            float* o = out + b * (KPAD * 5) + s * 5;
            o[0] = bb.x; o[1] = bb.y; o[2] = bb.z; o[3] = bb.w;
            o[4] = (float)(cl + 1);
        }
        if (lane == 0) {
            int nbase = BATCH * KPAD * 5;
            if (out_size >= nbase + BATCH)
                out[nbase + b] = (float)lim;
            g_ctr[b] = 0;   // self-reset for next graph replay
        }
    }
}

extern "C" void kernel_launch(void* const* d_in, const int* in_sizes, int n_in,
                              void* d_out, int out_size)
{
    (void)in_sizes; (void)n_in;
    const float* cls_prob  = (const float*)d_in[0];
    const float* rois      = (const float*)d_in[1];
    const float* bbox_pred = (const float*)d_in[2];
    const float* im_info   = (const float*)d_in[3];
    const float* thr       = (const float*)d_in[4];

    // raise dynamic smem cap (idempotent host call, capture-safe)
    cudaFuncSetAttribute(fused_nms_kernel,
                         cudaFuncAttributeMaxDynamicSharedMemorySize,
                         (int)sizeof(Smem));

    fused_nms_kernel<<<BATCH * NPAIR, NT, sizeof(Smem)>>>(
        cls_prob, rois, bbox_pred, im_info, thr, (float*)d_out, out_size);
}

// round 16
// speedup vs baseline: 1.4304x; 1.0092x over previous
#include <cuda_runtime.h>
#include <math.h>

// Problem constants (shapes fixed by the dataset)
#define BATCH 8
#define R 300
#define C 21
#define NC 20           // foreground classes
#define KPAD 21         // output pad size == num_classes
#define RW 10           // ceil(300/32) keep-bitmask words
#define RWP 11          // padded mask row stride (conflict-free: gcd(11,32)=1)
#define NMS_T 0.3f
#define NT 1024         // threads per block (2 independent halves of 512)
#define HT 512          // threads per half
#define NW 16           // warps per half
#define NPAIR (NC / 2)  // class pairs per image = blocks per image

// Cross-block intermediates (allocation-free rule: device globals)
__device__ float4   g_sb[BATCH * NC * R];      // sorted+clipped boxes per (b,class)
__device__ unsigned g_keep[BATCH * NC * RW];   // keep bitmask per (b,class)
__device__ int      g_ctr[BATCH];              // arrival counters (self-resetting)

struct Smem {
    float4  box[2][R];             // decoded boxes by original index
    float4  sb[2][R];              // boxes in sorted order (valid prefix)
    unsigned long long ckeys[2][R];// compacted valid keys (64-bit, stable fallback)
    unsigned k32[2][R];            // upper-32 score keys (fast rank path)
    float   area[2][R];            // areas in sorted order
    unsigned mask[2][R][RWP];      // suppression bitmask, padded rows
    int warpcnt[2][NW];
    int warpoff[2][NW];
    int sV[2];
    int sSum[2];
    int sOld[2];
    unsigned slive[2][RW], skept[2][RW], sknew[2][RW];
    unsigned skw[NC][RW];          // tail selection scratch
    int sexcl[32];
};

// Per-half barrier: ids 1 and 2 (0 is reserved for __syncthreads).
__device__ __forceinline__ void bar_half(int half) {
    asm volatile("bar.sync %0, %1;" :: "r"(half + 1), "r"(HT) : "memory");
}

__global__ __launch_bounds__(NT, 1) void fused_nms_kernel(
    const float* __restrict__ cls_prob,   // [B,R,C]
    const float* __restrict__ rois,       // [B,R,5]
    const float* __restrict__ bbox_pred,  // [B,R,4C]
    const float* __restrict__ im_info,    // [B,3]
    const float* __restrict__ thr_arr,    // [C]
    float* __restrict__ out, int out_size)
{
    extern __shared__ __align__(16) unsigned char smem_raw[];
    Smem& S = *reinterpret_cast<Smem*>(smem_raw);

    const int blk  = blockIdx.x;
    const int b    = blk / NPAIR;
    const int t    = threadIdx.x;
    const int half = t >> 9;                 // 0 or 1: which class of the pair
    const int tl   = t & (HT - 1);           // thread id within half
    const int lane = t & 31;
    const int wl   = tl >> 5;                // warp id within half (0..15)
    const int cc   = (blk % NPAIR) * 2 + half;   // 0..19
    const int c    = cc + 1;                 // class id 1..20

    if (tl == 0) S.sSum[half] = 0;           // ordered by first bar_half

    const float thr = thr_arr[c];
    const float H1 = im_info[b * 3 + 0] - 1.0f;
    const float W1 = im_info[b * 3 + 1] - 1.0f;

    // ---- decode + clip + key (one row per thread; arithmetic identical to R1) ----
    int valid = 0;
    unsigned long long key = ~0ULL;
    const int r = tl;
    if (r < R) {
        const float* rp = rois + (size_t)(b * R + r) * 5;
        float x1 = rp[1], y1 = rp[2], x2 = rp[3], y2 = rp[4];
        float w  = x2 - x1 + 1.0f;
        float h  = y2 - y1 + 1.0f;
        float cx = x1 + 0.5f * w;
        float cy = y1 + 0.5f * h;

        // 16B-aligned: byte offset = 336*(b*R+r) + 16*c
        const float4 d4 = *reinterpret_cast<const float4*>(
            bbox_pred + (size_t)(b * R + r) * (4 * C) + 4 * c);
        float d0 = d4.x * 0.1f;
        float d1 = d4.y * 0.1f;
        float d2 = d4.z * 0.2f;
        float d3 = d4.w * 0.2f;

        float pcx = d0 * w + cx;
        float pcy = d1 * h + cy;
        float pw  = expf(d2) * w;
        float ph  = expf(d3) * h;

        float bx1 = fminf(fmaxf(pcx - 0.5f * pw, 0.0f), W1);
        float by1 = fminf(fmaxf(pcy - 0.5f * ph, 0.0f), H1);
        float bx2 = fminf(fmaxf(pcx + 0.5f * pw, 0.0f), W1);
        float by2 = fminf(fmaxf(pcy + 0.5f * ph, 0.0f), H1);
        S.box[half][r] = make_float4(bx1, by1, bx2, by2);

        float s = cls_prob[(size_t)(b * R + r) * C + c];
        valid = (s > thr) ? 1 : 0;

        // monotone float->uint, inverted => ascending sort == descending score,
        // low 32 bits = original index (stable tie-break).
        unsigned u = __float_as_uint(s);
        unsigned m = (u & 0x80000000u) ? ~u : (u | 0x80000000u);
        key = (((unsigned long long)(~m)) << 32) | (unsigned)r;
    }

    // ---- stable compaction of valid rows per half (index order preserved) ----
    unsigned bal = __ballot_sync(0xffffffffu, valid);
    if (lane == 0) S.warpcnt[half][wl] = __popc(bal);
    bar_half(half);
    if (tl < NW) {
        int v = S.warpcnt[half][tl];
        int incl = v;
        #pragma unroll
        for (int off = 1; off < NW; off <<= 1) {
            int n = __shfl_up_sync(0x0000ffffu, incl, off);
            if (tl >= off) incl += n;
        }
        S.warpoff[half][tl] = incl - v;
        if (tl == NW - 1) S.sV[half] = incl;
    }
    bar_half(half);
    const int V  = S.sV[half];
    const int VW = (V + 31) >> 5;

    if (valid) {
        int pos = S.warpoff[half][wl] + __popc(bal & ((1u << lane) - 1u));
        S.ckeys[half][pos] = key;
        S.k32[half][pos]   = (unsigned)(key >> 32);
    }
    bar_half(half);

    // ---- fast 32-bit rank (+ exact tie detection via rank-sum invariant) ----
    // Ranks by strict-less on the 32-bit score key. Tie-free <=> ranks form a
    // permutation <=> sum(rank) == V(V-1)/2 (any tie strictly lowers the sum).
    int p = tl >> 1, hh = tl & 1, rkf = 0;
    if (V > 0 && V <= 256) {
        int pc = (p < V) ? p : (V - 1);
        unsigned k32i = S.k32[half][pc];
        int Vh = (V + 1) >> 1;
        int jlo = hh ? Vh : 0;
        int jhi = hh ? V : Vh;
        #pragma unroll 4
        for (int j = jlo; j < jhi; j++)
            rkf += (S.k32[half][j] < k32i);
        rkf += __shfl_xor_sync(0xffffffffu, rkf, 1);
        int contrib = (hh == 0 && p < V) ? rkf : 0;
        #pragma unroll
        for (int off = 16; off > 0; off >>= 1)
            contrib += __shfl_down_sync(0xffffffffu, contrib, off);
        if (lane == 0 && contrib) atomicAdd(&S.sSum[half], contrib);
    }
    bar_half(half);

    // ---- scatter into sorted order (fast path, or exact 64-bit on ties) ----
    if (V > 0) {
        bool fast = (V <= 256) && (S.sSum[half] == (V * (V - 1)) / 2);
        if (fast) {
            if (hh == 0 && p < V) {
                int orig = (int)(S.ckeys[half][p] & 0xFFFFFFFFu);
                float4 bb = S.box[half][orig];
                S.sb[half][rkf] = bb;
                S.area[half][rkf] = (bb.z - bb.x + 1.0f) * (bb.w - bb.y + 1.0f);
            }
        } else {
            // rare exact path: full stable 64-bit enumeration rank
            if (tl < V) {
                unsigned long long kp = S.ckeys[half][tl];
                int rk = 0;
                #pragma unroll 4
                for (int j = 0; j < V; j++)
                    rk += (S.ckeys[half][j] < kp);
                int orig = (int)(kp & 0xFFFFFFFFu);
                float4 bb = S.box[half][orig];
                S.sb[half][rk] = bb;
                S.area[half][rk] = (bb.z - bb.x + 1.0f) * (bb.w - bb.y + 1.0f);
            }
        }
    }
    // pre-zero mask rows (peeling reads full rows, including below-diagonal words)
    for (int idx = tl; idx < V * RWP; idx += HT)
        ((unsigned*)S.mask[half])[idx] = 0u;
    bar_half(half);

    // ---- publish sorted boxes (valid prefix) for cross-block selection ----
    if (tl < V)
        __stcg(&g_sb[(size_t)(b * NC + cc) * R + tl], S.sb[half][tl]);

    // ---- suppression bitmask, paired rows per warp, division-free compare ----
    //   iou > T  <=>  (1+T)*inter - T*(ai+aj) > 0 (reals). When |diff| is larger
    //   than 1e-5 * union (>> combined rounding), the fast form is exact;
    //   otherwise evaluate the reference's literal (inter/union) > T, hoisted
    //   behind a warp-uniform ballot so the division is branched over.
    for (int i = wl; i < V; i += 2 * NW) {
        const int i2 = i + NW;
        const bool has2 = (i2 < V);
        float4 bi  = S.sb[half][i];
        float  ai  = S.area[half][i];
        float4 bi2 = S.sb[half][has2 ? i2 : i];
        float  ai2 = S.area[half][has2 ? i2 : i];
        for (int jw = (i >> 5); jw < VW; jw++) {
            int j  = (jw << 5) + lane;
            int jc = (j < V) ? j : (V - 1);
            float4 bj = S.sb[half][jc];
            float  aj = S.area[half][jc];

            float inter1, un1, diff1, inter2, un2, diff2;
            bool sup1, sup2;
            {
                float ix1 = fmaxf(bi.x, bj.x);
                float iy1 = fmaxf(bi.y, bj.y);
                float ix2 = fminf(bi.z, bj.z);
                float iy2 = fminf(bi.w, bj.w);
                float iw = fmaxf(ix2 - ix1 + 1.0f, 0.0f);
                float ih = fmaxf(iy2 - iy1 + 1.0f, 0.0f);
                inter1 = iw * ih;
                float asum = ai + aj;
                diff1 = fmaf(inter1, 1.0f + NMS_T, -NMS_T * asum);
                un1   = asum - inter1;
                sup1  = diff1 > 0.0f;
            }
            {
                float ix1 = fmaxf(bi2.x, bj.x);
                float iy1 = fmaxf(bi2.y, bj.y);
                float ix2 = fminf(bi2.z, bj.z);
                float iy2 = fminf(bi2.w, bj.w);
                float iw = fmaxf(ix2 - ix1 + 1.0f, 0.0f);
                float ih = fmaxf(iy2 - iy1 + 1.0f, 0.0f);
                inter2 = iw * ih;
                float asum = ai2 + aj;
                diff2 = fmaf(inter2, 1.0f + NMS_T, -NMS_T * asum);
                un2   = asum - inter2;
                sup2  = diff2 > 0.0f;
            }
            bool need1 = fabsf(diff1) <= 1e-5f * un1;
            bool need2 = fabsf(diff2) <= 1e-5f * un2;
            if (__ballot_sync(0xffffffffu, need1 || need2)) {
                if (need1) sup1 = (inter1 / un1) > NMS_T;
                if (need2) sup2 = (inter2 / un2) > NMS_T;
            }
            sup1 = sup1 && (j > i)  && (j < V);
            sup2 = sup2 && has2 && (j > i2) && (j < V);

            unsigned bits1 = __ballot_sync(0xffffffffu, sup1);
            unsigned bits2 = __ballot_sync(0xffffffffu, sup2);
            if (lane == 0) {
                S.mask[half][i][jw] = bits1;
                if (has2) S.mask[half][i2][jw] = bits2;  // zero below diag: harmless
            }
        }
    }

    // ---- init peeling state ----
    if (tl < RW) {
        int lo = tl << 5, hi = min(V, lo + 32);
        unsigned lv = 0;
        if (hi > lo) lv = (hi - lo == 32) ? 0xffffffffu : ((1u << (hi - lo)) - 1u);
        S.slive[half][tl] = lv;
        S.skept[half][tl] = 0u;
    }
    bar_half(half);   // orders slive/skept/mask writes for this half

    // ---- exact parallel peeling NMS: independent per half, 2 barriers/round ----
    int alive = (V > 0);
    while (alive) {
        unsigned acc = 0;
        if (wl < RW) {
            for (int i = lane; i < V; i += 32)
                if ((S.slive[half][i >> 5] >> (i & 31)) & 1u) acc |= S.mask[half][i][wl];
            #pragma unroll
            for (int off = 16; off > 0; off >>= 1)
                acc |= __shfl_down_sync(0xffffffffu, acc, off);
            if (lane == 0) {
                unsigned kn = S.slive[half][wl] & ~acc;
                S.sknew[half][wl] = kn;
                S.skept[half][wl] |= kn;
            }
        }
        bar_half(half);                    // sknew visible; slive still old
        unsigned acc2 = 0;
        if (wl < RW) {
            for (int i = lane; i < V; i += 32)
                if ((S.sknew[half][i >> 5] >> (i & 31)) & 1u) acc2 |= S.mask[half][i][wl];
            #pragma unroll
            for (int off = 16; off > 0; off >>= 1)
                acc2 |= __shfl_down_sync(0xffffffffu, acc2, off);
            if (lane == 0)
                S.slive[half][wl] = S.slive[half][wl] & acc & ~acc2;  // acc in reg
        }
        bar_half(half);                    // updated slive visible
        unsigned any = 0;
        #pragma unroll
        for (int w2 = 0; w2 < RW; w2++) any |= S.slive[half][w2];
        alive = (any != 0u);               // uniform within the half
    }
    if (tl < RW)
        __stcg(&g_keep[(b * NC + cc) * RW + tl], S.skept[half][tl]);

    // ---- release writes, arrive; 20th-arriving half does selection ----
    __threadfence();
    bar_half(half);
    if (tl == 0) {
        S.sOld[half] = atomicAdd(&g_ctr[b], 1);
        __threadfence();
    }
    bar_half(half);

    if (S.sOld[half] == NC - 1 && tl < 32) {
        int cls = lane;     // 0..19 valid
        int cnt = 0;
        if (cls < NC) {
            #pragma unroll
            for (int w = 0; w < RW; w++) {
                unsigned kwv = __ldcg(&g_keep[(b * NC + cls) * RW + w]);
                S.skw[cls][w] = kwv;
                cnt += __popc(kwv);
            }
        }
        // warp inclusive scan of counts
        int incl = cnt;
        #pragma unroll
        for (int off = 1; off < 32; off <<= 1) {
            int n = __shfl_up_sync(0xffffffffu, incl, off);
            if (lane >= off) incl += n;
        }
        int total = __shfl_sync(0xffffffffu, incl, 31);
        S.sexcl[lane] = incl - cnt;
        __syncwarp();

        // zero this image's [K,5] slab
        for (int i = lane; i < KPAD * 5; i += 32)
            out[b * (KPAD * 5) + i] = 0.0f;
        __syncwarp();

        // slot-parallel emit: lane s owns output slot s
        int s = lane;
        int lim = min(total, KPAD);
        if (s < lim) {
            int cl = 0;
            #pragma unroll
            for (int c2 = 1; c2 < NC; c2++)
                if (S.sexcl[c2] <= s) cl = c2;
            int q = s - S.sexcl[cl];
            int w = 0;
            #pragma unroll
            for (int ww = 0; ww < RW; ww++) {
                int pc = __popc(S.skw[cl][ww]);
                bool here = (q < pc);
                if (!here) q -= pc;
                if (here) { w = ww; break; }
            }
            unsigned word = S.skw[cl][w];
            #pragma unroll
            for (int k = 0; k < 31; k++)
                if (k < q) word &= word - 1u;
            int bit = __ffs(word) - 1;
            float4 bb = __ldcg(&g_sb[(size_t)(b * NC + cl) * R + (w << 5) + bit]);
            float* o = out + b * (KPAD * 5) + s * 5;
            o[0] = bb.x; o[1] = bb.y; o[2] = bb.z; o[3] = bb.w;
            o[4] = (float)(cl + 1);
        }
        if (lane == 0) {
            int nbase = BATCH * KPAD * 5;
            if (out_size >= nbase + BATCH)
                out[nbase + b] = (float)lim;
            g_ctr[b] = 0;   // self-reset for next graph replay
        }
    }
}

extern "C" void kernel_launch(void* const* d_in, const int* in_sizes, int n_in,
                              void* d_out, int out_size)
{
    (void)in_sizes; (void)n_in;
    const float* cls_prob  = (const float*)d_in[0];
    const float* rois      = (const float*)d_in[1];
    const float* bbox_pred = (const float*)d_in[2];
    const float* im_info   = (const float*)d_in[3];
    const float* thr       = (const float*)d_in[4];

    // raise dynamic smem cap (idempotent host call, capture-safe)
    cudaFuncSetAttribute(fused_nms_kernel,
                         cudaFuncAttributeMaxDynamicSharedMemorySize,
                         (int)sizeof(Smem));

    fused_nms_kernel<<<BATCH * NPAIR, NT, sizeof(Smem)>>>(
        cls_prob, rois, bbox_pred, im_info, thr, (float*)d_out, out_size);
}